// round 1
// baseline (speedup 1.0000x reference)
#include <cuda_runtime.h>
#include <cstdint>

#define T_LEN   16384
#define T_MASK  16383
#define L_HALF  50
#define NMN     449
#define NK      11
#define NOUT    16284      // T - 2*L
#define TILE_T  256
#define THREADS 128
#define CHUNK   64
#define NCHUNK  8          // ceil(449/64)

// -------- device scratch (no allocations allowed) --------
__device__ int2   g_mn[NMN];
__device__ float4 g_coef[2][NMN][23];   // per pair: [cpU|cpV], then 11x {U1|V1, U2|V2}

// -------- packed f32x2 helpers (Blackwell FFMA2) --------
static __device__ __forceinline__ unsigned long long f2fma(unsigned long long a, unsigned long long b, unsigned long long c) {
    unsigned long long d;
    asm("fma.rn.f32x2 %0, %1, %2, %3;" : "=l"(d) : "l"(a), "l"(b), "l"(c));
    return d;
}
static __device__ __forceinline__ unsigned long long f2mul(unsigned long long a, unsigned long long b) {
    unsigned long long d;
    asm("mul.rn.f32x2 %0, %1, %2;" : "=l"(d) : "l"(a), "l"(b));
    return d;
}
static __device__ __forceinline__ unsigned long long pk2(float lo, float hi) {
    unsigned long long d;
    asm("mov.b64 %0, {%1, %2};" : "=l"(d) : "f"(lo), "f"(hi));
    return d;
}
static __device__ __forceinline__ float2 up2(unsigned long long v) {
    float2 r;
    asm("mov.b64 {%0, %1}, %2;" : "=f"(r.x), "=f"(r.y) : "l"(v));
    return r;
}
static __device__ __forceinline__ unsigned long long ng2(unsigned long long v) {
    return v ^ 0x8000000080000000ULL;   // negate both packed floats
}

// -------- build (m,n) pair table in reference enumeration order --------
__global__ void sopbc_build_mn() {
    int lane = threadIdx.x;
    int basecnt = 0;
    for (int c = 0; c < 82; ++c) {                // 82*32 = 2624 >= 51*51
        int cell = c * 32 + lane;
        int m = cell / 51 - 25;
        int n = cell % 51 - 25;
        bool valid = (cell < 2601) && (abs(m * n) <= 25);
        unsigned mask = __ballot_sync(0xffffffffu, valid);
        if (valid) {
            int pos = basecnt + __popc(mask & ((1u << lane) - 1u));
            g_mn[pos] = make_int2(m, n);
        }
        basecnt += __popc(mask);
    }
}

// -------- pack coefficients: select batch row, fold power factors, dual layout --------
__global__ void sopbc_pack(const float* __restrict__ ti,
                           const float* __restrict__ pbcr, const float* __restrict__ pbci,
                           const float* __restrict__ c1r,  const float* __restrict__ c1i,
                           const float* __restrict__ c2r,  const float* __restrict__ c2i) {
    int idx = blockIdx.x * blockDim.x + threadIdx.x;
    if (idx >= 2 * NMN) return;
    int b = idx / NMN;
    int p = idx % NMN;

    int xi = (int)(ti[b * 4 + 2] / 2.0e9f);
    int ind = 0;
    if (xi == 20) ind = 0;
    else if (xi == 40) ind = 1;
    else if (xi == 80) ind = 2;
    else if (xi == 160) ind = 3;

    float P  = exp10f(ti[b * 4 + 0] * 0.1f);
    float sp = sqrtf(P);
    float f3 = sp * sp * sp;
    float f5 = f3 * sp * sp;

    float4* dst = &g_coef[b][p][0];
    float cpr = f3 * pbcr[ind * NMN + p];
    float cpi = f3 * pbci[ind * NMN + p];
    dst[0] = make_float4(cpr, cpi, -cpi, cpr);

    int cb = ind * (NMN * NK) + p * NK;
#pragma unroll
    for (int j = 0; j < NK; ++j) {
        float u1 = f5 * c1r[cb + j], w1 = f5 * c1i[cb + j];
        float u2 = f5 * c2r[cb + j], w2 = f5 * c2i[cb + j];
        dst[1 + 2 * j] = make_float4(u1, w1, -w1, u1);   // A * C1
        dst[2 + 2 * j] = make_float4(u2, w2, w2, -u2);   // conj(A) * C2
    }
}

// -------- main kernel: one batch per blockIdx.y, 256 t's per block, 2 t's per thread --------
__global__ __launch_bounds__(THREADS, 1)
void sopbc_main(const float* __restrict__ Er, const float* __restrict__ Ei,
                float* __restrict__ out) {
    __shared__ float2 sE[360];
    __shared__ int2   s_mn[NMN];
    __shared__ float4 s_cf[CHUNK * 23];

    const int tid  = threadIdx.x;
    const int b    = blockIdx.y;
    const int bx   = blockIdx.x;
    const int base = b * T_LEN;
    const int win0 = bx * TILE_T;          // global t of sE[0] is win0 (t = to + 50, window = t-50)

    for (int i = tid; i < 356; i += THREADS) {
        int t = (win0 + i) & T_MASK;
        sE[i] = make_float2(Er[base + t], Ei[base + t]);
    }
    for (int i = tid; i < NMN; i += THREADS) s_mn[i] = g_mn[i];

    unsigned long long G1a[NK], G1b[NK], G2a[NK], G2b[NK];
    unsigned long long acc1 = 0ull, acc2 = 0ull;
#pragma unroll
    for (int j = 0; j < NK; ++j) { G1a[j] = G1b[j] = G2a[j] = G2b[j] = 0ull; }

    const int i1 = tid + L_HALF;           // sE index of t1
    const int i2 = tid + 128 + L_HALF;     // sE index of t2

    const float4* gsrc = &g_coef[b][0][0];

    for (int ch = 0; ch < NCHUNK; ++ch) {
        const int p0 = ch * CHUNK;
        const int np = (NMN - p0 < CHUNK) ? (NMN - p0) : CHUNK;
        __syncthreads();
        {
            const float4* src = gsrc + p0 * 23;
            const int cnt = np * 23;
            for (int i = tid; i < cnt; i += THREADS) s_cf[i] = src[i];
        }
        __syncthreads();

        for (int p = 0; p < np; ++p) {
            const int2 mn = s_mn[p0 + p];
            const int m = mn.x, n = mn.y;

            // A = E(t-n) * conj(E(t-m-n)) * E(t-m), packed across (t1, t2)
            float2 av1 = sE[i1 - n],     av2 = sE[i2 - n];
            float2 bv1 = sE[i1 - m - n], bv2 = sE[i2 - m - n];
            float2 cv1 = sE[i1 - m],     cv2 = sE[i2 - m];

            unsigned long long ar = pk2(av1.x, av2.x), ai = pk2(av1.y, av2.y);
            unsigned long long br = pk2(bv1.x, bv2.x), bi = pk2(bv1.y, bv2.y);
            unsigned long long cr = pk2(cv1.x, cv2.x), ci = pk2(cv1.y, cv2.y);

            unsigned long long ur  = f2fma(ai, bi, f2mul(ar, br));          // ar*br + ai*bi
            unsigned long long ui  = f2fma(ai, br, f2mul(ng2(ar), bi));     // ai*br - ar*bi
            unsigned long long Arr = f2fma(ng2(ui), ci, f2mul(ur, cr));     // ur*cr - ui*ci
            unsigned long long Aii = f2fma(ur, ci, f2mul(ui, cr));          // ur*ci + ui*cr

            float2 arp = up2(Arr), aip = up2(Aii);
            unsigned long long R1 = pk2(arp.x, arp.x), I1 = pk2(aip.x, aip.x);
            unsigned long long R2 = pk2(arp.y, arp.y), I2 = pk2(aip.y, aip.y);

            const ulonglong2* cf = reinterpret_cast<const ulonglong2*>(s_cf + p * 23);
            ulonglong2 c0 = cf[0];
            acc1 = f2fma(I1, c0.y, f2fma(R1, c0.x, acc1));
            acc2 = f2fma(I2, c0.y, f2fma(R2, c0.x, acc2));
#pragma unroll
            for (int j = 0; j < NK; ++j) {
                ulonglong2 cA = cf[1 + 2 * j];
                ulonglong2 cB = cf[2 + 2 * j];
                G1a[j] = f2fma(I1, cA.y, f2fma(R1, cA.x, G1a[j]));
                G1b[j] = f2fma(I2, cA.y, f2fma(R2, cA.x, G1b[j]));
                G2a[j] = f2fma(I1, cB.y, f2fma(R1, cB.x, G2a[j]));
                G2b[j] = f2fma(I2, cB.y, f2fma(R2, cB.x, G2b[j]));
            }
        }
    }

    // ---- epilogue: E2 = sum_k I*G1 + Q*G2 ; Eo = E + cp + E2 ----
    // t1 (always valid: max to1 = 63*256+127 = 16255 < 16284)
    {
        float2 e0 = sE[i1];
        float2 cp = up2(acc1);
        float er = e0.x + cp.x, eim = e0.y + cp.y;
        float sr = 0.f, si = 0.f;
#pragma unroll
        for (int j = 0; j < NK; ++j) {
            float2 e  = sE[i1 + 5 - j];            // E[t - (j-5)]
            float Iv  = e.x * e.x + e.y * e.y;
            float Qr  = e.x * e.x - e.y * e.y;
            float Qi  = 2.f * e.x * e.y;
            float2 g1 = up2(G1a[j]);
            float2 g2 = up2(G2a[j]);
            sr += Iv * g1.x + Qr * g2.x - Qi * g2.y;
            si += Iv * g1.y + Qr * g2.y + Qi * g2.x;
        }
        int to = win0 + tid;
        out[(b * NOUT + to) * 2 + 0] = er + sr;
        out[(b * NOUT + to) * 2 + 1] = eim + si;
    }
    // t2 (guarded)
    {
        int to = win0 + tid + 128;
        if (to < NOUT) {
            float2 e0 = sE[i2];
            float2 cp = up2(acc2);
            float er = e0.x + cp.x, eim = e0.y + cp.y;
            float sr = 0.f, si = 0.f;
#pragma unroll
            for (int j = 0; j < NK; ++j) {
                float2 e  = sE[i2 + 5 - j];
                float Iv  = e.x * e.x + e.y * e.y;
                float Qr  = e.x * e.x - e.y * e.y;
                float Qi  = 2.f * e.x * e.y;
                float2 g1 = up2(G1b[j]);
                float2 g2 = up2(G2b[j]);
                sr += Iv * g1.x + Qr * g2.x - Qi * g2.y;
                si += Iv * g1.y + Qr * g2.y + Qi * g2.x;
            }
            out[(b * NOUT + to) * 2 + 0] = er + sr;
            out[(b * NOUT + to) * 2 + 1] = eim + si;
        }
    }
}

extern "C" void kernel_launch(void* const* d_in, const int* in_sizes, int n_in,
                              void* d_out, int out_size) {
    const float* Er   = (const float*)d_in[0];
    const float* Ei   = (const float*)d_in[1];
    const float* ti   = (const float*)d_in[2];
    const float* pbcr = (const float*)d_in[3];
    const float* pbci = (const float*)d_in[4];
    const float* c1r  = (const float*)d_in[5];
    const float* c1i  = (const float*)d_in[6];
    const float* c2r  = (const float*)d_in[7];
    const float* c2i  = (const float*)d_in[8];
    float* out = (float*)d_out;

    sopbc_build_mn<<<1, 32>>>();
    sopbc_pack<<<(2 * NMN + 127) / 128, 128>>>(ti, pbcr, pbci, c1r, c1i, c2r, c2i);

    dim3 grid(64, 2);
    sopbc_main<<<grid, THREADS>>>(Er, Ei, out);
}

// round 5
// speedup vs baseline: 1.0298x; 1.0298x over previous
#include <cuda_runtime.h>
#include <cstdint>

#define T_LEN   16384
#define T_MASK  16383
#define L_HALF  50
#define NMN     449
#define NK      11
#define NOUT    16284      // T - 2*L
#define TILE_T  256
#define THREADS 256
#define CHUNK   64
#define NCHUNK  8          // ceil(449/64)

// -------- compile-time (m,n) pair table (reference enumeration order) --------
struct MNTab { short m[NMN]; short n[NMN]; };
constexpr MNTab make_mn() {
    MNTab t{};
    int c = 0;
    for (int m = -25; m <= 25; ++m)
        for (int n = -25; n <= 25; ++n) {
            int p = m * n; if (p < 0) p = -p;
            if (p <= 25) { t.m[c] = (short)m; t.n[c] = (short)n; ++c; }
        }
    return t;
}
__constant__ MNTab c_mn = make_mn();

// -------- device scratch (no allocations allowed) --------
// per pair layout: [0]=cp, [1..11]=C1_j, [12..22]=C2_j
__device__ float4 g_coef[2][NMN][23];

// -------- packed f32x2 helpers (Blackwell FFMA2) --------
static __device__ __forceinline__ unsigned long long f2fma(unsigned long long a, unsigned long long b, unsigned long long c) {
    unsigned long long d;
    asm("fma.rn.f32x2 %0, %1, %2, %3;" : "=l"(d) : "l"(a), "l"(b), "l"(c));
    return d;
}
static __device__ __forceinline__ unsigned long long f2mul(unsigned long long a, unsigned long long b) {
    unsigned long long d;
    asm("mul.rn.f32x2 %0, %1, %2;" : "=l"(d) : "l"(a), "l"(b));
    return d;
}
static __device__ __forceinline__ unsigned long long pk2(float lo, float hi) {
    unsigned long long d;
    asm("mov.b64 %0, {%1, %2};" : "=l"(d) : "f"(lo), "f"(hi));
    return d;
}
static __device__ __forceinline__ float2 up2(unsigned long long v) {
    float2 r;
    asm("mov.b64 {%0, %1}, %2;" : "=f"(r.x), "=f"(r.y) : "l"(v));
    return r;
}
static __device__ __forceinline__ unsigned long long ng2(unsigned long long v) {
    return v ^ 0x8000000080000000ULL;
}

// -------- pack coefficients: select batch row, fold power factors, dual layout --------
__global__ void sopbc_pack(const float* __restrict__ ti,
                           const float* __restrict__ pbcr, const float* __restrict__ pbci,
                           const float* __restrict__ c1r,  const float* __restrict__ c1i,
                           const float* __restrict__ c2r,  const float* __restrict__ c2i) {
    int idx = blockIdx.x * blockDim.x + threadIdx.x;
    if (idx >= 2 * NMN) return;
    int b = idx / NMN;
    int p = idx % NMN;

    int xi = (int)(ti[b * 4 + 2] / 2.0e9f);
    int ind = 0;
    if (xi == 20) ind = 0;
    else if (xi == 40) ind = 1;
    else if (xi == 80) ind = 2;
    else if (xi == 160) ind = 3;

    float P  = exp10f(ti[b * 4 + 0] * 0.1f);
    float sp = sqrtf(P);
    float f3 = sp * sp * sp;
    float f5 = f3 * sp * sp;

    float4* dst = &g_coef[b][p][0];
    float cpr = f3 * pbcr[ind * NMN + p];
    float cpi = f3 * pbci[ind * NMN + p];
    dst[0] = make_float4(cpr, cpi, -cpi, cpr);

    int cb = ind * (NMN * NK) + p * NK;
#pragma unroll
    for (int j = 0; j < NK; ++j) {
        float u1 = f5 * c1r[cb + j], w1 = f5 * c1i[cb + j];
        float u2 = f5 * c2r[cb + j], w2 = f5 * c2i[cb + j];
        dst[1 + j]  = make_float4(u1, w1, -w1, u1);   // A * C1
        dst[12 + j] = make_float4(u2, w2, w2, -u2);   // conj(A) * C2
    }
}

// -------- main kernel --------
// blockIdx.y = batch, blockIdx.x = t-tile (256 t's). 256 threads:
//   warps 0-3 (g=0): slot = tid&127, compute A, cp-acc, G1 (A*C1), final store
//   warps 4-7 (g=1): same slots, compute A, G2 (conj(A)*C2), partial via smem
// Each thread covers t1 = win0+slot and t2 = win0+slot+128 (ILP2, f32x2-packed).
__global__ __launch_bounds__(THREADS, 1)
void sopbc_main(const float* __restrict__ Er, const float* __restrict__ Ei,
                float* __restrict__ out) {
    __shared__ float2 sE[356];
    __shared__ float4 s_cf[CHUNK * 23];
    __shared__ float4 s_red[128];

    const int tid  = threadIdx.x;
    const int slot = tid & 127;
    const int g    = tid >> 7;
    const int b    = blockIdx.y;
    const int bx   = blockIdx.x;
    const int base = b * T_LEN;
    const int win0 = bx * TILE_T;

    for (int i = tid; i < 356; i += THREADS) {
        int t = (win0 + i) & T_MASK;
        sE[i] = make_float2(Er[base + t], Ei[base + t]);
    }

    unsigned long long X[NK], Y[NK];
    unsigned long long A0 = 0ull, A1 = 0ull;
#pragma unroll
    for (int j = 0; j < NK; ++j) { X[j] = Y[j] = 0ull; }

    const int i1 = slot + L_HALF;
    const int i2 = slot + 128 + L_HALF;

    const float4* gsrc = &g_coef[b][0][0];

    for (int ch = 0; ch < NCHUNK; ++ch) {
        const int p0 = ch * CHUNK;
        const int np = (NMN - p0 < CHUNK) ? (NMN - p0) : CHUNK;
        __syncthreads();
        {
            const float4* src = gsrc + p0 * 23;
            const int cnt = np * 23;
            for (int i = tid; i < cnt; i += THREADS) s_cf[i] = src[i];
        }
        __syncthreads();

        if (g == 0) {
            for (int p = 0; p < np; ++p) {
                const int m = c_mn.m[p0 + p], n = c_mn.n[p0 + p];
                float2 av1 = sE[i1 - n],     av2 = sE[i2 - n];
                float2 bv1 = sE[i1 - m - n], bv2 = sE[i2 - m - n];
                float2 cv1 = sE[i1 - m],     cv2 = sE[i2 - m];

                unsigned long long ar = pk2(av1.x, av2.x), ai = pk2(av1.y, av2.y);
                unsigned long long br = pk2(bv1.x, bv2.x), bi = pk2(bv1.y, bv2.y);
                unsigned long long cr = pk2(cv1.x, cv2.x), ci = pk2(cv1.y, cv2.y);

                unsigned long long ur  = f2fma(ai, bi, f2mul(ar, br));
                unsigned long long ui  = f2fma(ai, br, f2mul(ng2(ar), bi));
                unsigned long long Arr = f2fma(ng2(ui), ci, f2mul(ur, cr));
                unsigned long long Aii = f2fma(ur, ci, f2mul(ui, cr));

                float2 arp = up2(Arr), aip = up2(Aii);
                unsigned long long R1 = pk2(arp.x, arp.x), I1 = pk2(aip.x, aip.x);
                unsigned long long R2 = pk2(arp.y, arp.y), I2 = pk2(aip.y, aip.y);

                const ulonglong2* cf = reinterpret_cast<const ulonglong2*>(s_cf + p * 23);
                ulonglong2 c0 = cf[0];
                A0 = f2fma(I1, c0.y, f2fma(R1, c0.x, A0));
                A1 = f2fma(I2, c0.y, f2fma(R2, c0.x, A1));
#pragma unroll
                for (int j = 0; j < NK; ++j) {
                    ulonglong2 c = cf[1 + j];
                    X[j] = f2fma(I1, c.y, f2fma(R1, c.x, X[j]));
                    Y[j] = f2fma(I2, c.y, f2fma(R2, c.x, Y[j]));
                }
            }
        } else {
            for (int p = 0; p < np; ++p) {
                const int m = c_mn.m[p0 + p], n = c_mn.n[p0 + p];
                float2 av1 = sE[i1 - n],     av2 = sE[i2 - n];
                float2 bv1 = sE[i1 - m - n], bv2 = sE[i2 - m - n];
                float2 cv1 = sE[i1 - m],     cv2 = sE[i2 - m];

                unsigned long long ar = pk2(av1.x, av2.x), ai = pk2(av1.y, av2.y);
                unsigned long long br = pk2(bv1.x, bv2.x), bi = pk2(bv1.y, bv2.y);
                unsigned long long cr = pk2(cv1.x, cv2.x), ci = pk2(cv1.y, cv2.y);

                unsigned long long ur  = f2fma(ai, bi, f2mul(ar, br));
                unsigned long long ui  = f2fma(ai, br, f2mul(ng2(ar), bi));
                unsigned long long Arr = f2fma(ng2(ui), ci, f2mul(ur, cr));
                unsigned long long Aii = f2fma(ur, ci, f2mul(ui, cr));

                float2 arp = up2(Arr), aip = up2(Aii);
                unsigned long long R1 = pk2(arp.x, arp.x), I1 = pk2(aip.x, aip.x);
                unsigned long long R2 = pk2(arp.y, arp.y), I2 = pk2(aip.y, aip.y);

                const ulonglong2* cf = reinterpret_cast<const ulonglong2*>(s_cf + p * 23);
#pragma unroll
                for (int j = 0; j < NK; ++j) {
                    ulonglong2 c = cf[12 + j];
                    X[j] = f2fma(I1, c.y, f2fma(R1, c.x, X[j]));
                    Y[j] = f2fma(I2, c.y, f2fma(R2, c.x, Y[j]));
                }
            }
        }
    }

    // ---- epilogue ----
    if (g == 1) {
        // partial: sum_j Q * G2  (Q = E^2 at t-k)
        float pr1 = 0.f, pi1 = 0.f, pr2 = 0.f, pi2 = 0.f;
#pragma unroll
        for (int j = 0; j < NK; ++j) {
            float2 e1 = sE[i1 + 5 - j];
            float Qr1 = e1.x * e1.x - e1.y * e1.y;
            float Qi1 = 2.f * e1.x * e1.y;
            float2 g2 = up2(X[j]);
            pr1 += Qr1 * g2.x - Qi1 * g2.y;
            pi1 += Qr1 * g2.y + Qi1 * g2.x;

            float2 e2 = sE[i2 + 5 - j];
            float Qr2 = e2.x * e2.x - e2.y * e2.y;
            float Qi2 = 2.f * e2.x * e2.y;
            float2 h2 = up2(Y[j]);
            pr2 += Qr2 * h2.x - Qi2 * h2.y;
            pi2 += Qr2 * h2.y + Qi2 * h2.x;
        }
        s_red[slot] = make_float4(pr1, pi1, pr2, pi2);
    }
    __syncthreads();
    if (g == 0) {
        float4 r = s_red[slot];
        // t1 (always valid: max to1 = 63*256+127 = 16255 < 16284)
        {
            float2 e0 = sE[i1];
            float2 cp = up2(A0);
            float sr = 0.f, si = 0.f;
#pragma unroll
            for (int j = 0; j < NK; ++j) {
                float2 e  = sE[i1 + 5 - j];
                float Iv  = e.x * e.x + e.y * e.y;
                float2 g1 = up2(X[j]);
                sr += Iv * g1.x;
                si += Iv * g1.y;
            }
            int to = win0 + slot;
            out[(b * NOUT + to) * 2 + 0] = e0.x + cp.x + sr + r.x;
            out[(b * NOUT + to) * 2 + 1] = e0.y + cp.y + si + r.y;
        }
        // t2 (guarded)
        {
            int to = win0 + slot + 128;
            if (to < NOUT) {
                float2 e0 = sE[i2];
                float2 cp = up2(A1);
                float sr = 0.f, si = 0.f;
#pragma unroll
                for (int j = 0; j < NK; ++j) {
                    float2 e  = sE[i2 + 5 - j];
                    float Iv  = e.x * e.x + e.y * e.y;
                    float2 g1 = up2(Y[j]);
                    sr += Iv * g1.x;
                    si += Iv * g1.y;
                }
                out[(b * NOUT + to) * 2 + 0] = e0.x + cp.x + sr + r.z;
                out[(b * NOUT + to) * 2 + 1] = e0.y + cp.y + si + r.w;
            }
        }
    }
}

extern "C" void kernel_launch(void* const* d_in, const int* in_sizes, int n_in,
                              void* d_out, int out_size) {
    const float* Er   = (const float*)d_in[0];
    const float* Ei   = (const float*)d_in[1];
    const float* ti   = (const float*)d_in[2];
    const float* pbcr = (const float*)d_in[3];
    const float* pbci = (const float*)d_in[4];
    const float* c1r  = (const float*)d_in[5];
    const float* c1i  = (const float*)d_in[6];
    const float* c2r  = (const float*)d_in[7];
    const float* c2i  = (const float*)d_in[8];
    float* out = (float*)d_out;

    sopbc_pack<<<(2 * NMN + 127) / 128, 128>>>(ti, pbcr, pbci, c1r, c1i, c2r, c2i);

    dim3 grid(64, 2);
    sopbc_main<<<grid, THREADS>>>(Er, Ei, out);
}